// round 2
// baseline (speedup 1.0000x reference)
#include <cuda_runtime.h>
#include <cstdint>

// ---------------- problem constants ----------------
#define S_LEN 2048
#define BATCH 16
#define DIM   1024
#define M_TOT (S_LEN*BATCH)      // 32768
#define N_TOT (3*DIM)            // 3072
#define K_TOT DIM                // 1024

// GEMM tiling
#define BM 128
#define BN 128
#define BK 16
#define KSTEPS (K_TOT/BK)        // 64
#define STRIDE 20                // smem row stride in floats (16 + 4 pad -> conflict-free frags)

// scan partitioning
#define SEGS 32
#define SEGLEN (S_LEN/SEGS)      // 64
#define CH (BATCH*DIM)           // 16384

// ---------------- device scratch ----------------
__device__ float g_yact[(size_t)M_TOT * N_TOT];   // activated gates: tanh(Z), sig(F), sig(O)
__device__ float g_Xr[(size_t)M_TOT * K_TOT];     // tf32-rna rounded X
__device__ float g_Wr[(size_t)N_TOT * K_TOT];     // tf32-rna rounded W
__device__ float g_seg_a[SEGS*CH];
__device__ float g_seg_c[SEGS*CH];
__device__ float g_seg_s[SEGS*CH];

// ---------------- helpers ----------------
__device__ __forceinline__ uint32_t smem_u32(const void* p) {
    uint32_t a;
    asm("{ .reg .u64 t; cvta.to.shared.u64 t, %1; cvt.u32.u64 %0, t; }" : "=r"(a) : "l"(p));
    return a;
}
__device__ __forceinline__ float round_tf32(float x) {
    uint32_t r; asm("cvt.rna.tf32.f32 %0, %1;" : "=r"(r) : "f"(x));
    return __uint_as_float(r);
}
__device__ __forceinline__ void cp_async16(uint32_t dst, const void* src) {
    asm volatile("cp.async.cg.shared.global [%0], [%1], 16;" :: "r"(dst), "l"(src) : "memory");
}
__device__ __forceinline__ void cp_commit() {
    asm volatile("cp.async.commit_group;" ::: "memory");
}
__device__ __forceinline__ void cp_wait1() {
    asm volatile("cp.async.wait_group 1;" ::: "memory");
}
__device__ __forceinline__ void cp_wait0() {
    asm volatile("cp.async.wait_group 0;" ::: "memory");
}

// mma.sync m16n8k8 tf32, fp32 accumulate (baseline PTX, sm_80+)
__device__ __forceinline__ void mma_tf32(float* d, const uint32_t* a, const uint32_t* b) {
    asm volatile(
        "mma.sync.aligned.m16n8k8.row.col.f32.tf32.tf32.f32 "
        "{%0,%1,%2,%3}, {%4,%5,%6,%7}, {%8,%9}, {%0,%1,%2,%3};"
        : "+f"(d[0]), "+f"(d[1]), "+f"(d[2]), "+f"(d[3])
        : "r"(a[0]), "r"(a[1]), "r"(a[2]), "r"(a[3]), "r"(b[0]), "r"(b[1]));
}

__device__ __forceinline__ float fsigmoid(float x) { return 1.0f / (1.0f + __expf(-x)); }
__device__ __forceinline__ float ftanh(float x)    { return 2.0f * fsigmoid(2.0f * x) - 1.0f; }

// ============================================================
// Kernel 0: tf32-rna pre-rounding (streamed, float4)
// ============================================================
__global__ void __launch_bounds__(256)
round_pass(const float* __restrict__ src, float* __restrict__ dst, int n4) {
    int i = blockIdx.x * 256 + threadIdx.x;
    if (i >= n4) return;
    float4 v = ((const float4*)src)[i];
    v.x = round_tf32(v.x); v.y = round_tf32(v.y);
    v.z = round_tf32(v.z); v.w = round_tf32(v.w);
    ((float4*)dst)[i] = v;
}

// ============================================================
// Kernel 1: Y = act(X @ W^T + b)  via mma.sync tf32
//   grid = (N_TOT/BN, M_TOT/BM) = (24, 256), 256 threads (8 warps, 2x4)
// ============================================================
__global__ void __launch_bounds__(256)
gemm_gates(const float* __restrict__ bias) {
    __shared__ float As[2][BM * STRIDE];
    __shared__ float Bs[2][BN * STRIDE];

    const int tid  = threadIdx.x;
    const int lane = tid & 31;
    const int wid  = tid >> 5;
    const int wm   = wid & 1;           // 0..1  -> 64-row slice
    const int wn   = wid >> 1;          // 0..3  -> 32-col slice
    const int m0   = blockIdx.y * BM;
    const int n0   = blockIdx.x * BN;
    const int gate = blockIdx.x >> 3;   // 0=Z(tanh) 1=F(sig) 2=O(sig)

    const int lrow = lane >> 2;         // 0..7
    const int lcol = lane & 3;          // 0..3

    float acc[4][4][4];
    #pragma unroll
    for (int i = 0; i < 4; i++)
        #pragma unroll
        for (int j = 0; j < 4; j++)
            #pragma unroll
            for (int c = 0; c < 4; c++) acc[i][j][c] = 0.0f;

    // cp.async fill: 512 16B ops per tile per matrix; 2 per thread
    const int o0 = tid, o1 = tid + 256;
    const int rA0 = o0 >> 2, cA0 = o0 & 3;
    const int rA1 = o1 >> 2, cA1 = o1 & 3;

    auto issue = [&](int kt, int buf) {
        const float* xb = g_Xr + (size_t)m0 * K_TOT + kt * BK;
        const float* wb = g_Wr + (size_t)n0 * K_TOT + kt * BK;
        cp_async16(smem_u32(&As[buf][rA0 * STRIDE + cA0 * 4]), xb + (size_t)rA0 * K_TOT + cA0 * 4);
        cp_async16(smem_u32(&Bs[buf][rA0 * STRIDE + cA0 * 4]), wb + (size_t)rA0 * K_TOT + cA0 * 4);
        cp_async16(smem_u32(&As[buf][rA1 * STRIDE + cA1 * 4]), xb + (size_t)rA1 * K_TOT + cA1 * 4);
        cp_async16(smem_u32(&Bs[buf][rA1 * STRIDE + cA1 * 4]), wb + (size_t)rA1 * K_TOT + cA1 * 4);
        cp_commit();
    };

    issue(0, 0);

    for (int kt = 0; kt < KSTEPS; kt++) {
        const int buf = kt & 1;
        if (kt < KSTEPS - 1) { issue(kt + 1, buf ^ 1); cp_wait1(); }
        else                 { cp_wait0(); }
        __syncthreads();

        const float* Aw = &As[buf][(wm * 64) * STRIDE];
        const float* Bw = &Bs[buf][(wn * 32) * STRIDE];

        #pragma unroll
        for (int ks = 0; ks < 2; ks++) {
            const int kb = ks * 8;
            uint32_t a[4][4], b[4][2];
            #pragma unroll
            for (int i = 0; i < 4; i++) {
                a[i][0] = __float_as_uint(Aw[(i * 16 + lrow)     * STRIDE + kb + lcol]);
                a[i][1] = __float_as_uint(Aw[(i * 16 + lrow + 8) * STRIDE + kb + lcol]);
                a[i][2] = __float_as_uint(Aw[(i * 16 + lrow)     * STRIDE + kb + lcol + 4]);
                a[i][3] = __float_as_uint(Aw[(i * 16 + lrow + 8) * STRIDE + kb + lcol + 4]);
            }
            #pragma unroll
            for (int j = 0; j < 4; j++) {
                b[j][0] = __float_as_uint(Bw[(j * 8 + lrow) * STRIDE + kb + lcol]);
                b[j][1] = __float_as_uint(Bw[(j * 8 + lrow) * STRIDE + kb + lcol + 4]);
            }
            #pragma unroll
            for (int i = 0; i < 4; i++)
                #pragma unroll
                for (int j = 0; j < 4; j++)
                    mma_tf32(acc[i][j], a[i], b[j]);
        }
        __syncthreads();
    }

    // epilogue: bias + activation, direct float2 stores (32B-sector aligned per quad)
    #pragma unroll
    for (int j = 0; j < 4; j++) {
        const int n = n0 + wn * 32 + j * 8 + lcol * 2;
        const float b0 = __ldg(bias + n);
        const float b1 = __ldg(bias + n + 1);
        #pragma unroll
        for (int i = 0; i < 4; i++) {
            const int m = m0 + wm * 64 + i * 16 + lrow;
            float y0 = acc[i][j][0] + b0, y1 = acc[i][j][1] + b1;
            float y2 = acc[i][j][2] + b0, y3 = acc[i][j][3] + b1;
            float2 v0, v1;
            if (gate == 0) {
                v0 = make_float2(ftanh(y0), ftanh(y1));
                v1 = make_float2(ftanh(y2), ftanh(y3));
            } else {
                v0 = make_float2(fsigmoid(y0), fsigmoid(y1));
                v1 = make_float2(fsigmoid(y2), fsigmoid(y3));
            }
            *(float2*)&g_yact[(size_t)m * N_TOT + n]       = v0;
            *(float2*)&g_yact[(size_t)(m + 8) * N_TOT + n] = v1;
        }
    }
}

// ============================================================
// Kernel 2: per-segment affine reduction (a = prod(1-f), c = local scan from 0)
// ============================================================
__global__ void __launch_bounds__(128)
scan_partial() {
    const int g = blockIdx.x * 128 + threadIdx.x;       // seg*CH + ch
    const int seg = g >> 14;                            // /CH
    const int ch  = g & (CH - 1);
    const int b = ch >> 10, d = ch & (DIM - 1);
    float a = 1.0f, c = 0.0f;
    const int t0 = seg * SEGLEN;
    #pragma unroll 4
    for (int t = t0; t < t0 + SEGLEN; t++) {
        size_t m = (size_t)(t * BATCH + b);
        float z = g_yact[m * N_TOT + d];
        float f = g_yact[m * N_TOT + DIM + d];
        c = fmaf(f, z - c, c);
        a *= (1.0f - f);
    }
    g_seg_a[g] = a;
    g_seg_c[g] = c;
}

// ============================================================
// Kernel 3: sequential combine over 32 segments; emits segment start states + C_last
// ============================================================
__global__ void __launch_bounds__(128)
scan_combine(const float* __restrict__ hidden, float* __restrict__ c_last) {
    const int ch = blockIdx.x * 128 + threadIdx.x;      // 0..CH
    float s = hidden[ch];
    #pragma unroll
    for (int p = 0; p < SEGS; p++) {
        g_seg_s[p * CH + ch] = s;
        s = fmaf(g_seg_a[p * CH + ch], s, g_seg_c[p * CH + ch]);
    }
    c_last[ch] = s;
}

// ============================================================
// Kernel 4: replay segments from start state, write H = sig(O) * C
// ============================================================
__global__ void __launch_bounds__(128)
scan_final(float* __restrict__ H) {
    const int g = blockIdx.x * 128 + threadIdx.x;
    const int seg = g >> 14;
    const int ch  = g & (CH - 1);
    const int b = ch >> 10, d = ch & (DIM - 1);
    float h = g_seg_s[g];
    const int t0 = seg * SEGLEN;
    #pragma unroll 4
    for (int t = t0; t < t0 + SEGLEN; t++) {
        size_t m = (size_t)(t * BATCH + b);
        float z = g_yact[m * N_TOT + d];
        float f = g_yact[m * N_TOT + DIM + d];
        float o = g_yact[m * N_TOT + 2 * DIM + d];
        h = fmaf(f, z - h, h);
        H[m * DIM + d] = o * h;
    }
}

// ============================================================
// launcher
// ============================================================
extern "C" void kernel_launch(void* const* d_in, const int* in_sizes, int n_in,
                              void* d_out, int out_size) {
    const float* X      = (const float*)d_in[0];   // (S,B,D)
    const float* hidden = (const float*)d_in[1];   // (B,D)
    const float* W      = (const float*)d_in[2];   // (3D,D)
    const float* b      = (const float*)d_in[3];   // (3D,)
    float* out = (float*)d_out;                    // H (S,B,D) then C_last (1,B,D)

    float* xr; cudaGetSymbolAddress((void**)&xr, g_Xr);
    float* wr; cudaGetSymbolAddress((void**)&wr, g_Wr);

    round_pass<<<(M_TOT * K_TOT / 4 + 255) / 256, 256>>>(X, xr, M_TOT * K_TOT / 4);
    round_pass<<<(N_TOT * K_TOT / 4 + 255) / 256, 256>>>(W, wr, N_TOT * K_TOT / 4);

    dim3 grid(N_TOT / BN, M_TOT / BM);             // (24, 256)
    gemm_gates<<<grid, 256>>>(b);

    scan_partial<<<SEGS * CH / 128, 128>>>();
    scan_combine<<<CH / 128, 128>>>(hidden, out + (size_t)M_TOT * DIM);
    scan_final<<<SEGS * CH / 128, 128>>>(out);
}

// round 3
// speedup vs baseline: 1.2733x; 1.2733x over previous
#include <cuda_runtime.h>
#include <cstdint>

// ---------------- problem constants ----------------
#define S_LEN 2048
#define BATCH 16
#define DIM   1024
#define M_TOT (S_LEN*BATCH)      // 32768
#define N_TOT (3*DIM)            // 3072
#define K_TOT DIM                // 1024

// GEMM tiling
#define BM 256
#define BN 128
#define BK 32
#define KSTEPS (K_TOT/BK)        // 32
#define NSTAGE 3
#define SA_BYTES (BM*BK*4)       // 32768 per stage
#define SB_BYTES (BN*BK*4)       // 16384 per stage
#define SMEM_TOTAL (NSTAGE*(SA_BYTES+SB_BYTES))   // 147456

// scan partitioning
#define SEGS 32
#define SEGLEN (S_LEN/SEGS)      // 64
#define CH (BATCH*DIM)           // 16384

// ---------------- device scratch ----------------
__device__ float g_yact[(size_t)M_TOT * N_TOT];   // activated gates: tanh(Z), sig(F), sig(O)
__device__ float g_Xr[(size_t)M_TOT * K_TOT];     // tf32-rna rounded X
__device__ float g_Wr[(size_t)N_TOT * K_TOT];     // tf32-rna rounded W
__device__ float g_seg_a[SEGS*CH];
__device__ float g_seg_c[SEGS*CH];
__device__ float g_seg_s[SEGS*CH];

// ---------------- helpers ----------------
__device__ __forceinline__ uint32_t smem_u32(const void* p) {
    uint32_t a;
    asm("{ .reg .u64 t; cvta.to.shared.u64 t, %1; cvt.u32.u64 %0, t; }" : "=r"(a) : "l"(p));
    return a;
}
__device__ __forceinline__ float round_tf32(float x) {
    uint32_t r; asm("cvt.rna.tf32.f32 %0, %1;" : "=r"(r) : "f"(x));
    return __uint_as_float(r);
}
__device__ __forceinline__ void cp_async16(uint32_t dst, const void* src) {
    asm volatile("cp.async.cg.shared.global [%0], [%1], 16;" :: "r"(dst), "l"(src) : "memory");
}
__device__ __forceinline__ void cp_commit() {
    asm volatile("cp.async.commit_group;" ::: "memory");
}
__device__ __forceinline__ void cp_wait1() {
    asm volatile("cp.async.wait_group 1;" ::: "memory");
}

// ldmatrix x4 (bit-mover; on fp32 data: thread t of each 8-lane group gets
// f32 element (row t/4, col t%4) of an 8x4-float tile == tf32 fragment layout)
__device__ __forceinline__ void ldsm_x4(uint32_t* r, uint32_t addr) {
    asm volatile("ldmatrix.sync.aligned.m8n8.x4.shared.b16 {%0,%1,%2,%3}, [%4];"
        : "=r"(r[0]), "=r"(r[1]), "=r"(r[2]), "=r"(r[3]) : "r"(addr));
}

// mma.sync m16n8k8 tf32, fp32 accumulate (baseline PTX, sm_80+)
__device__ __forceinline__ void mma_tf32(float* d, const uint32_t* a, const uint32_t* b) {
    asm volatile(
        "mma.sync.aligned.m16n8k8.row.col.f32.tf32.tf32.f32 "
        "{%0,%1,%2,%3}, {%4,%5,%6,%7}, {%8,%9}, {%0,%1,%2,%3};"
        : "+f"(d[0]), "+f"(d[1]), "+f"(d[2]), "+f"(d[3])
        : "r"(a[0]), "r"(a[1]), "r"(a[2]), "r"(a[3]), "r"(b[0]), "r"(b[1]));
}

__device__ __forceinline__ float fsigmoid(float x) { return 1.0f / (1.0f + __expf(-x)); }
__device__ __forceinline__ float ftanh(float x)    { return 2.0f * fsigmoid(2.0f * x) - 1.0f; }

// ============================================================
// Kernel 0: tf32-rna pre-rounding (streamed, float4)
// ============================================================
__global__ void __launch_bounds__(256)
round_pass(const float* __restrict__ src, float* __restrict__ dst, int n4) {
    int i = blockIdx.x * 256 + threadIdx.x;
    if (i >= n4) return;
    float4 v = ((const float4*)src)[i];
    v.x = round_tf32(v.x); v.y = round_tf32(v.y);
    v.z = round_tf32(v.z); v.w = round_tf32(v.w);
    ((float4*)dst)[i] = v;
}

// ============================================================
// Kernel 1: Y = act(X @ W^T + b)  via mma.sync tf32 + ldmatrix + 3-stage cp.async
//   grid = (N_TOT/BN, M_TOT/BM) = (24, 128), 512 threads (16 warps, 4m x 4n)
//   smem: SW128 swizzle, 128B rows of 32 floats
// ============================================================
__global__ void __launch_bounds__(512, 1)
gemm_gates(const float* __restrict__ bias) {
    extern __shared__ char smem[];
    const uint32_t sA0 = smem_u32(smem);                    // 3 stages of A
    const uint32_t sB0 = sA0 + NSTAGE * SA_BYTES;           // 3 stages of B

    const int tid  = threadIdx.x;
    const int lane = tid & 31;
    const int wid  = tid >> 5;          // 0..15
    const int wm   = wid & 3;           // 64-row slice
    const int wn   = wid >> 2;          // 32-col slice
    const int m0   = blockIdx.y * BM;
    const int n0   = blockIdx.x * BN;
    const int gate = blockIdx.x >> 3;   // 0=Z(tanh) 1=F(sig) 2=O(sig)

    float acc[4][4][4];
    #pragma unroll
    for (int i = 0; i < 4; i++)
        #pragma unroll
        for (int j = 0; j < 4; j++)
            #pragma unroll
            for (int c = 0; c < 4; c++) acc[i][j][c] = 0.0f;

    // ---- cp.async fill mapping (16B chunks, SW128 swizzle) ----
    // A: 2048 chunks (256 rows x 8), 4 per thread; B: 1024 chunks, 2 per thread
    auto issue = [&](int kt, int buf) {
        const uint32_t sA = sA0 + buf * SA_BYTES;
        const uint32_t sB = sB0 + buf * SB_BYTES;
        const float* xb = g_Xr + (size_t)m0 * K_TOT + kt * BK;
        const float* wb = g_Wr + (size_t)n0 * K_TOT + kt * BK;
        #pragma unroll
        for (int i = 0; i < 4; i++) {
            int id = tid + i * 512;
            int r = id >> 3, c = id & 7;
            cp_async16(sA + r * 128 + (((uint32_t)(c ^ (r & 7))) << 4),
                       xb + (size_t)r * K_TOT + c * 4);
        }
        #pragma unroll
        for (int i = 0; i < 2; i++) {
            int id = tid + i * 512;
            int r = id >> 3, c = id & 7;
            cp_async16(sB + r * 128 + (((uint32_t)(c ^ (r & 7))) << 4),
                       wb + (size_t)r * K_TOT + c * 4);
        }
        cp_commit();
    };

    // ---- per-lane fragment address precompute ----
    const int l7 = lane & 7;
    // A: sub-tile s = lane>>3: rows wm*64 + i*16 + (s&1)*8 + l7 ; chunk = ks*2 + (s>>1)
    const int aRowBase = wm * 64 + ((lane >> 3) & 1) * 8 + l7;   // + i*16
    const int aChunkAdd = (lane >> 4);                            // 0 or 1
    // B: sub-tile s: rows wn*32 + (jb + (s>>1))*8 + l7 ; chunk = ks*2 + (s&1)
    const int bRowBase = wn * 32 + (lane >> 4) * 8 + l7;          // + jb*8
    const int bChunkAdd = ((lane >> 3) & 1);

    issue(0, 0);
    issue(1, 1);

    for (int kt = 0; kt < KSTEPS; kt++) {
        cp_wait1();
        __syncthreads();
        const int nb = kt + 2;
        if (nb < KSTEPS) issue(nb, nb % NSTAGE);
        else             cp_commit();           // keep group count consistent

        const int buf = kt % NSTAGE;
        const uint32_t sA = sA0 + buf * SA_BYTES;
        const uint32_t sB = sB0 + buf * SB_BYTES;

        #pragma unroll
        for (int ks = 0; ks < 4; ks++) {
            uint32_t a[4][4], b[4][2];
            const int ac = ks * 2 + aChunkAdd;
            #pragma unroll
            for (int i = 0; i < 4; i++) {
                const int row = aRowBase + i * 16;
                ldsm_x4(a[i], sA + row * 128 + (((uint32_t)(ac ^ l7)) << 4));
            }
            const int bc = ks * 2 + bChunkAdd;
            #pragma unroll
            for (int jb = 0; jb < 2; jb++) {
                uint32_t r[4];
                const int row = bRowBase + jb * 16;   // covers j = jb*2 + (s>>1)
                ldsm_x4(r, sB + row * 128 + (((uint32_t)(bc ^ l7)) << 4));
                b[jb * 2 + 0][0] = r[0]; b[jb * 2 + 0][1] = r[1];
                b[jb * 2 + 1][0] = r[2]; b[jb * 2 + 1][1] = r[3];
            }
            #pragma unroll
            for (int i = 0; i < 4; i++)
                #pragma unroll
                for (int j = 0; j < 4; j++)
                    mma_tf32(acc[i][j], a[i], b[j]);
        }
        __syncthreads();   // protect buf reuse by next issue()
    }

    // ---- epilogue: bias + activation, float2 stores ----
    const int lrow = lane >> 2, lcol = lane & 3;
    #pragma unroll
    for (int j = 0; j < 4; j++) {
        const int n = n0 + wn * 32 + j * 8 + lcol * 2;
        const float b0 = __ldg(bias + n);
        const float b1 = __ldg(bias + n + 1);
        #pragma unroll
        for (int i = 0; i < 4; i++) {
            const int m = m0 + wm * 64 + i * 16 + lrow;
            float y0 = acc[i][j][0] + b0, y1 = acc[i][j][1] + b1;
            float y2 = acc[i][j][2] + b0, y3 = acc[i][j][3] + b1;
            float2 v0, v1;
            if (gate == 0) {
                v0 = make_float2(ftanh(y0), ftanh(y1));
                v1 = make_float2(ftanh(y2), ftanh(y3));
            } else {
                v0 = make_float2(fsigmoid(y0), fsigmoid(y1));
                v1 = make_float2(fsigmoid(y2), fsigmoid(y3));
            }
            *(float2*)&g_yact[(size_t)m * N_TOT + n]       = v0;
            *(float2*)&g_yact[(size_t)(m + 8) * N_TOT + n] = v1;
        }
    }
}

// ============================================================
// Kernel 2: per-segment affine reduction (a = prod(1-f), c = local scan from 0)
// ============================================================
__global__ void __launch_bounds__(128)
scan_partial() {
    const int g = blockIdx.x * 128 + threadIdx.x;       // seg*CH + ch
    const int seg = g >> 14;                            // /CH
    const int ch  = g & (CH - 1);
    const int b = ch >> 10, d = ch & (DIM - 1);
    float a = 1.0f, c = 0.0f;
    const int t0 = seg * SEGLEN;
    #pragma unroll 4
    for (int t = t0; t < t0 + SEGLEN; t++) {
        size_t m = (size_t)(t * BATCH + b);
        float z = g_yact[m * N_TOT + d];
        float f = g_yact[m * N_TOT + DIM + d];
        c = fmaf(f, z - c, c);
        a *= (1.0f - f);
    }
    g_seg_a[g] = a;
    g_seg_c[g] = c;
}

// ============================================================
// Kernel 3: sequential combine over 32 segments; emits segment start states + C_last
// ============================================================
__global__ void __launch_bounds__(128)
scan_combine(const float* __restrict__ hidden, float* __restrict__ c_last) {
    const int ch = blockIdx.x * 128 + threadIdx.x;      // 0..CH
    float s = hidden[ch];
    #pragma unroll
    for (int p = 0; p < SEGS; p++) {
        g_seg_s[p * CH + ch] = s;
        s = fmaf(g_seg_a[p * CH + ch], s, g_seg_c[p * CH + ch]);
    }
    c_last[ch] = s;
}

// ============================================================
// Kernel 4: replay segments from start state, write H = sig(O) * C
// ============================================================
__global__ void __launch_bounds__(128)
scan_final(float* __restrict__ H) {
    const int g = blockIdx.x * 128 + threadIdx.x;
    const int seg = g >> 14;
    const int ch  = g & (CH - 1);
    const int b = ch >> 10, d = ch & (DIM - 1);
    float h = g_seg_s[g];
    const int t0 = seg * SEGLEN;
    #pragma unroll 4
    for (int t = t0; t < t0 + SEGLEN; t++) {
        size_t m = (size_t)(t * BATCH + b);
        float z = g_yact[m * N_TOT + d];
        float f = g_yact[m * N_TOT + DIM + d];
        float o = g_yact[m * N_TOT + 2 * DIM + d];
        h = fmaf(f, z - h, h);
        H[m * DIM + d] = o * h;
    }
}

// ============================================================
// launcher
// ============================================================
extern "C" void kernel_launch(void* const* d_in, const int* in_sizes, int n_in,
                              void* d_out, int out_size) {
    const float* X      = (const float*)d_in[0];   // (S,B,D)
    const float* hidden = (const float*)d_in[1];   // (B,D)
    const float* W      = (const float*)d_in[2];   // (3D,D)
    const float* b      = (const float*)d_in[3];   // (3D,)
    float* out = (float*)d_out;                    // H (S,B,D) then C_last (1,B,D)

    float* xr; cudaGetSymbolAddress((void**)&xr, g_Xr);
    float* wr; cudaGetSymbolAddress((void**)&wr, g_Wr);

    static bool attr_set = false;
    if (!attr_set) {
        cudaFuncSetAttribute(gemm_gates, cudaFuncAttributeMaxDynamicSharedMemorySize, SMEM_TOTAL);
        attr_set = true;
    }

    round_pass<<<(M_TOT * K_TOT / 4 + 255) / 256, 256>>>(X, xr, M_TOT * K_TOT / 4);
    round_pass<<<(N_TOT * K_TOT / 4 + 255) / 256, 256>>>(W, wr, N_TOT * K_TOT / 4);

    dim3 grid(N_TOT / BN, M_TOT / BM);             // (24, 128)
    gemm_gates<<<grid, 512, SMEM_TOTAL>>>(b);

    scan_partial<<<SEGS * CH / 128, 128>>>();
    scan_combine<<<CH / 128, 128>>>(hidden, out + (size_t)M_TOT * DIM);
    scan_final<<<SEGS * CH / 128, 128>>>(out);
}

// round 4
// speedup vs baseline: 1.3178x; 1.0349x over previous
#include <cuda_runtime.h>
#include <cstdint>

// ---------------- problem constants ----------------
#define S_LEN 2048
#define BATCH 16
#define DIM   1024
#define M_TOT (S_LEN*BATCH)      // 32768
#define N_TOT (3*DIM)            // 3072
#define K_TOT DIM                // 1024

// GEMM tiling
#define BM 256
#define BN 128
#define BK 32
#define KSTEPS (K_TOT/BK)        // 32
#define NSTAGE 4
#define LOOKAHEAD 3
#define SA_BYTES (BM*BK*4)       // 32768 per stage
#define SB_BYTES (BN*BK*4)       // 16384 per stage
#define SMEM_TOTAL (NSTAGE*(SA_BYTES+SB_BYTES))   // 196608

// scan partitioning
#define SEGS 32
#define SEGLEN (S_LEN/SEGS)      // 64
#define CH (BATCH*DIM)           // 16384

// ---------------- device scratch ----------------
__device__ float g_yact[(size_t)M_TOT * N_TOT];   // activated gates: tanh(Z), sig(F), sig(O)
__device__ float g_Xr[(size_t)M_TOT * K_TOT];     // tf32-rna rounded X
__device__ float g_Wr[(size_t)N_TOT * K_TOT];     // tf32-rna rounded W
__device__ float g_seg_a[SEGS*CH];
__device__ float g_seg_c[SEGS*CH];
__device__ float g_seg_s[SEGS*CH];

// ---------------- helpers ----------------
__device__ __forceinline__ uint32_t smem_u32(const void* p) {
    uint32_t a;
    asm("{ .reg .u64 t; cvta.to.shared.u64 t, %1; cvt.u32.u64 %0, t; }" : "=r"(a) : "l"(p));
    return a;
}
__device__ __forceinline__ float round_tf32(float x) {
    uint32_t r; asm("cvt.rna.tf32.f32 %0, %1;" : "=r"(r) : "f"(x));
    return __uint_as_float(r);
}
__device__ __forceinline__ void cp_async16(uint32_t dst, const void* src) {
    asm volatile("cp.async.cg.shared.global [%0], [%1], 16;" :: "r"(dst), "l"(src) : "memory");
}
__device__ __forceinline__ void cp_commit() {
    asm volatile("cp.async.commit_group;" ::: "memory");
}
__device__ __forceinline__ void cp_wait2() {
    asm volatile("cp.async.wait_group 2;" ::: "memory");
}

// ldmatrix x4 (bit-mover; on fp32 data: thread t of each 8-lane group gets
// f32 element (row t/4, col t%4) of an 8x4-float tile == tf32 fragment layout)
__device__ __forceinline__ void ldsm_x4(uint32_t* r, uint32_t addr) {
    asm volatile("ldmatrix.sync.aligned.m8n8.x4.shared.b16 {%0,%1,%2,%3}, [%4];"
        : "=r"(r[0]), "=r"(r[1]), "=r"(r[2]), "=r"(r[3]) : "r"(addr));
}

// mma.sync m16n8k8 tf32, fp32 accumulate (baseline PTX, sm_80+)
__device__ __forceinline__ void mma_tf32(float* d, const uint32_t* a, const uint32_t* b) {
    asm volatile(
        "mma.sync.aligned.m16n8k8.row.col.f32.tf32.tf32.f32 "
        "{%0,%1,%2,%3}, {%4,%5,%6,%7}, {%8,%9}, {%0,%1,%2,%3};"
        : "+f"(d[0]), "+f"(d[1]), "+f"(d[2]), "+f"(d[3])
        : "r"(a[0]), "r"(a[1]), "r"(a[2]), "r"(a[3]), "r"(b[0]), "r"(b[1]));
}

__device__ __forceinline__ float fsigmoid(float x) { return 1.0f / (1.0f + __expf(-x)); }
__device__ __forceinline__ float ftanh(float x)    { return 2.0f * fsigmoid(2.0f * x) - 1.0f; }

// ============================================================
// Kernel 0: tf32-rna pre-rounding (streamed, float4)
// ============================================================
__global__ void __launch_bounds__(256)
round_pass(const float* __restrict__ src, float* __restrict__ dst, int n4) {
    int i = blockIdx.x * 256 + threadIdx.x;
    if (i >= n4) return;
    float4 v = ((const float4*)src)[i];
    v.x = round_tf32(v.x); v.y = round_tf32(v.y);
    v.z = round_tf32(v.z); v.w = round_tf32(v.w);
    ((float4*)dst)[i] = v;
}

// ============================================================
// Kernel 1: Y = act(X @ W^T + b)  via mma.sync tf32 + ldmatrix + 4-stage cp.async
//   grid = (N_TOT/BN, M_TOT/BM) = (24, 128), 512 threads (16 warps, 4m x 4n)
//   smem: SW128 swizzle, 128B rows of 32 floats; ONE barrier per k-tile
// ============================================================
__global__ void __launch_bounds__(512, 1)
gemm_gates(const float* __restrict__ bias) {
    extern __shared__ char smem[];
    const uint32_t sA0 = smem_u32(smem);                    // 4 stages of A
    const uint32_t sB0 = sA0 + NSTAGE * SA_BYTES;           // 4 stages of B

    const int tid  = threadIdx.x;
    const int lane = tid & 31;
    const int wid  = tid >> 5;          // 0..15
    const int wm   = wid & 3;           // 64-row slice
    const int wn   = wid >> 2;          // 32-col slice
    const int m0   = blockIdx.y * BM;
    const int n0   = blockIdx.x * BN;
    const int gate = blockIdx.x >> 3;   // 0=Z(tanh) 1=F(sig) 2=O(sig)

    float acc[4][4][4];
    #pragma unroll
    for (int i = 0; i < 4; i++)
        #pragma unroll
        for (int j = 0; j < 4; j++)
            #pragma unroll
            for (int c = 0; c < 4; c++) acc[i][j][c] = 0.0f;

    // ---- cp.async fill mapping (16B chunks, SW128 swizzle) ----
    auto issue = [&](int kt, int buf) {
        const uint32_t sA = sA0 + buf * SA_BYTES;
        const uint32_t sB = sB0 + buf * SB_BYTES;
        const float* xb = g_Xr + (size_t)m0 * K_TOT + kt * BK;
        const float* wb = g_Wr + (size_t)n0 * K_TOT + kt * BK;
        #pragma unroll
        for (int i = 0; i < 4; i++) {
            int id = tid + i * 512;
            int r = id >> 3, c = id & 7;
            cp_async16(sA + r * 128 + (((uint32_t)(c ^ (r & 7))) << 4),
                       xb + (size_t)r * K_TOT + c * 4);
        }
        #pragma unroll
        for (int i = 0; i < 2; i++) {
            int id = tid + i * 512;
            int r = id >> 3, c = id & 7;
            cp_async16(sB + r * 128 + (((uint32_t)(c ^ (r & 7))) << 4),
                       wb + (size_t)r * K_TOT + c * 4);
        }
        cp_commit();
    };

    // ---- per-lane fragment address precompute ----
    const int l7 = lane & 7;
    const int aRowBase = wm * 64 + ((lane >> 3) & 1) * 8 + l7;   // + i*16
    const int aChunkAdd = (lane >> 4);                            // 0 or 1
    const int bRowBase = wn * 32 + (lane >> 4) * 8 + l7;          // + jb*16
    const int bChunkAdd = ((lane >> 3) & 1);

    issue(0, 0);
    issue(1, 1);
    issue(2, 2);

    for (int kt = 0; kt < KSTEPS; kt++) {
        cp_wait2();                              // group kt complete
        __syncthreads();                         // also protects WAR for issue below
        const int nb = kt + LOOKAHEAD;
        if (nb < KSTEPS) issue(nb, nb % NSTAGE);
        else             cp_commit();            // keep group count consistent

        const int buf = kt % NSTAGE;
        const uint32_t sA = sA0 + buf * SA_BYTES;
        const uint32_t sB = sB0 + buf * SB_BYTES;

        #pragma unroll
        for (int ks = 0; ks < 4; ks++) {
            uint32_t a[4][4], b[4][2];
            const int ac = ks * 2 + aChunkAdd;
            #pragma unroll
            for (int i = 0; i < 4; i++) {
                const int row = aRowBase + i * 16;
                ldsm_x4(a[i], sA + row * 128 + (((uint32_t)(ac ^ l7)) << 4));
            }
            const int bc = ks * 2 + bChunkAdd;
            #pragma unroll
            for (int jb = 0; jb < 2; jb++) {
                uint32_t r[4];
                const int row = bRowBase + jb * 16;
                ldsm_x4(r, sB + row * 128 + (((uint32_t)(bc ^ l7)) << 4));
                b[jb * 2 + 0][0] = r[0]; b[jb * 2 + 0][1] = r[1];
                b[jb * 2 + 1][0] = r[2]; b[jb * 2 + 1][1] = r[3];
            }
            #pragma unroll
            for (int i = 0; i < 4; i++)
                #pragma unroll
                for (int j = 0; j < 4; j++)
                    mma_tf32(acc[i][j], a[i], b[j]);
        }
        // no trailing barrier: next iteration's wait+sync covers buffer reuse
    }

    // ---- epilogue: bias + activation, float2 stores ----
    const int lrow = lane >> 2, lcol = lane & 3;
    #pragma unroll
    for (int j = 0; j < 4; j++) {
        const int n = n0 + wn * 32 + j * 8 + lcol * 2;
        const float b0 = __ldg(bias + n);
        const float b1 = __ldg(bias + n + 1);
        #pragma unroll
        for (int i = 0; i < 4; i++) {
            const int m = m0 + wm * 64 + i * 16 + lrow;
            float y0 = acc[i][j][0] + b0, y1 = acc[i][j][1] + b1;
            float y2 = acc[i][j][2] + b0, y3 = acc[i][j][3] + b1;
            float2 v0, v1;
            if (gate == 0) {
                v0 = make_float2(ftanh(y0), ftanh(y1));
                v1 = make_float2(ftanh(y2), ftanh(y3));
            } else {
                v0 = make_float2(fsigmoid(y0), fsigmoid(y1));
                v1 = make_float2(fsigmoid(y2), fsigmoid(y3));
            }
            *(float2*)&g_yact[(size_t)m * N_TOT + n]       = v0;
            *(float2*)&g_yact[(size_t)(m + 8) * N_TOT + n] = v1;
        }
    }
}

// ============================================================
// Kernel 2: per-segment affine reduction (a = prod(1-f), c = local scan from 0)
// ============================================================
__global__ void __launch_bounds__(128)
scan_partial() {
    const int g = blockIdx.x * 128 + threadIdx.x;       // seg*CH + ch
    const int seg = g >> 14;                            // /CH
    const int ch  = g & (CH - 1);
    const int b = ch >> 10, d = ch & (DIM - 1);
    float a = 1.0f, c = 0.0f;
    const int t0 = seg * SEGLEN;
    #pragma unroll 4
    for (int t = t0; t < t0 + SEGLEN; t++) {
        size_t m = (size_t)(t * BATCH + b);
        float z = g_yact[m * N_TOT + d];
        float f = g_yact[m * N_TOT + DIM + d];
        c = fmaf(f, z - c, c);
        a *= (1.0f - f);
    }
    g_seg_a[g] = a;
    g_seg_c[g] = c;
}

// ============================================================
// Kernel 3: sequential combine over 32 segments; emits segment start states + C_last
// ============================================================
__global__ void __launch_bounds__(128)
scan_combine(const float* __restrict__ hidden, float* __restrict__ c_last) {
    const int ch = blockIdx.x * 128 + threadIdx.x;      // 0..CH
    float s = hidden[ch];
    #pragma unroll
    for (int p = 0; p < SEGS; p++) {
        g_seg_s[p * CH + ch] = s;
        s = fmaf(g_seg_a[p * CH + ch], s, g_seg_c[p * CH + ch]);
    }
    c_last[ch] = s;
}

// ============================================================
// Kernel 4: replay segments from start state, write H = sig(O) * C
// ============================================================
__global__ void __launch_bounds__(128)
scan_final(float* __restrict__ H) {
    const int g = blockIdx.x * 128 + threadIdx.x;
    const int seg = g >> 14;
    const int ch  = g & (CH - 1);
    const int b = ch >> 10, d = ch & (DIM - 1);
    float h = g_seg_s[g];
    const int t0 = seg * SEGLEN;
    #pragma unroll 4
    for (int t = t0; t < t0 + SEGLEN; t++) {
        size_t m = (size_t)(t * BATCH + b);
        float z = g_yact[m * N_TOT + d];
        float f = g_yact[m * N_TOT + DIM + d];
        float o = g_yact[m * N_TOT + 2 * DIM + d];
        h = fmaf(f, z - h, h);
        H[m * DIM + d] = o * h;
    }
}

// ============================================================
// launcher
// ============================================================
extern "C" void kernel_launch(void* const* d_in, const int* in_sizes, int n_in,
                              void* d_out, int out_size) {
    const float* X      = (const float*)d_in[0];   // (S,B,D)
    const float* hidden = (const float*)d_in[1];   // (B,D)
    const float* W      = (const float*)d_in[2];   // (3D,D)
    const float* b      = (const float*)d_in[3];   // (3D,)
    float* out = (float*)d_out;                    // H (S,B,D) then C_last (1,B,D)

    float* xr; cudaGetSymbolAddress((void**)&xr, g_Xr);
    float* wr; cudaGetSymbolAddress((void**)&wr, g_Wr);

    cudaFuncSetAttribute(gemm_gates, cudaFuncAttributeMaxDynamicSharedMemorySize, SMEM_TOTAL);

    round_pass<<<(M_TOT * K_TOT / 4 + 255) / 256, 256>>>(X, xr, M_TOT * K_TOT / 4);
    round_pass<<<(N_TOT * K_TOT / 4 + 255) / 256, 256>>>(W, wr, N_TOT * K_TOT / 4);

    dim3 grid(N_TOT / BN, M_TOT / BM);             // (24, 128)
    gemm_gates<<<grid, 512, SMEM_TOTAL>>>(b);

    scan_partial<<<SEGS * CH / 128, 128>>>();
    scan_combine<<<CH / 128, 128>>>(hidden, out + (size_t)M_TOT * DIM);
    scan_final<<<SEGS * CH / 128, 128>>>(out);
}

// round 5
// speedup vs baseline: 1.3819x; 1.0486x over previous
#include <cuda_runtime.h>
#include <cuda_fp16.h>
#include <cstdint>

// ---------------- problem constants ----------------
#define S_LEN 2048
#define BATCH 16
#define DIM   1024
#define M_TOT (S_LEN*BATCH)      // 32768
#define N_TOT (3*DIM)            // 3072
#define K_TOT DIM                // 1024

// GEMM tiling
#define BM 256
#define BN 128
#define BK 32
#define KSTEPS (K_TOT/BK)        // 32
#define NSTAGE 4
#define LOOKAHEAD 3
#define SA_BYTES (BM*BK*4)       // 32768 per stage
#define SB_BYTES (BN*BK*4)       // 16384 per stage
#define SMEM_TOTAL (NSTAGE*(SA_BYTES+SB_BYTES))   // 196608

// scan partitioning
#define SEGS 32
#define SEGLEN (S_LEN/SEGS)      // 64
#define CH (BATCH*DIM)           // 16384
#define CH2 (CH/2)               // 8192 channel-pairs

// ---------------- device scratch ----------------
__device__ __half g_yact[(size_t)M_TOT * N_TOT]; // activated gates (fp16): tanh(Z), sig(F), sig(O)
__device__ float g_Xr[(size_t)M_TOT * K_TOT];    // tf32-rna rounded X
__device__ float g_Wr[(size_t)N_TOT * K_TOT];    // tf32-rna rounded W
__device__ float g_seg_a[SEGS*CH];
__device__ float g_seg_c[SEGS*CH];
__device__ float g_seg_s[SEGS*CH];

// ---------------- helpers ----------------
__device__ __forceinline__ uint32_t smem_u32(const void* p) {
    uint32_t a;
    asm("{ .reg .u64 t; cvta.to.shared.u64 t, %1; cvt.u32.u64 %0, t; }" : "=r"(a) : "l"(p));
    return a;
}
__device__ __forceinline__ float round_tf32(float x) {
    uint32_t r; asm("cvt.rna.tf32.f32 %0, %1;" : "=r"(r) : "f"(x));
    return __uint_as_float(r);
}
__device__ __forceinline__ void cp_async16(uint32_t dst, const void* src) {
    asm volatile("cp.async.cg.shared.global [%0], [%1], 16;" :: "r"(dst), "l"(src) : "memory");
}
__device__ __forceinline__ void cp_commit() {
    asm volatile("cp.async.commit_group;" ::: "memory");
}
__device__ __forceinline__ void cp_wait2() {
    asm volatile("cp.async.wait_group 2;" ::: "memory");
}

// ldmatrix x4 (bit-mover; on fp32 data: thread t of each 8-lane group gets
// f32 element (row t/4, col t%4) of an 8x4-float tile == tf32 fragment layout)
__device__ __forceinline__ void ldsm_x4(uint32_t* r, uint32_t addr) {
    asm volatile("ldmatrix.sync.aligned.m8n8.x4.shared.b16 {%0,%1,%2,%3}, [%4];"
        : "=r"(r[0]), "=r"(r[1]), "=r"(r[2]), "=r"(r[3]) : "r"(addr));
}

// mma.sync m16n8k8 tf32, fp32 accumulate (baseline PTX, sm_80+)
__device__ __forceinline__ void mma_tf32(float* d, const uint32_t* a, const uint32_t* b) {
    asm volatile(
        "mma.sync.aligned.m16n8k8.row.col.f32.tf32.tf32.f32 "
        "{%0,%1,%2,%3}, {%4,%5,%6,%7}, {%8,%9}, {%0,%1,%2,%3};"
        : "+f"(d[0]), "+f"(d[1]), "+f"(d[2]), "+f"(d[3])
        : "r"(a[0]), "r"(a[1]), "r"(a[2]), "r"(a[3]), "r"(b[0]), "r"(b[1]));
}

__device__ __forceinline__ float fsigmoid(float x) { return 1.0f / (1.0f + __expf(-x)); }
__device__ __forceinline__ float ftanh(float x)    { return 2.0f * fsigmoid(2.0f * x) - 1.0f; }

// ============================================================
// Kernel 0: tf32-rna pre-rounding (streamed, float4)
// ============================================================
__global__ void __launch_bounds__(256)
round_pass(const float* __restrict__ src, float* __restrict__ dst, int n4) {
    int i = blockIdx.x * 256 + threadIdx.x;
    if (i >= n4) return;
    float4 v = ((const float4*)src)[i];
    v.x = round_tf32(v.x); v.y = round_tf32(v.y);
    v.z = round_tf32(v.z); v.w = round_tf32(v.w);
    ((float4*)dst)[i] = v;
}

// ============================================================
// Kernel 1: Y = act(X @ W^T + b)  via mma.sync tf32 + ldmatrix + 4-stage cp.async
//   grid = (N_TOT/BN, M_TOT/BM) = (24, 128), 512 threads (16 warps, 4m x 4n)
// ============================================================
__global__ void __launch_bounds__(512, 1)
gemm_gates(const float* __restrict__ bias) {
    extern __shared__ char smem[];
    const uint32_t sA0 = smem_u32(smem);                    // 4 stages of A
    const uint32_t sB0 = sA0 + NSTAGE * SA_BYTES;           // 4 stages of B

    const int tid  = threadIdx.x;
    const int lane = tid & 31;
    const int wid  = tid >> 5;          // 0..15
    const int wm   = wid & 3;           // 64-row slice
    const int wn   = wid >> 2;          // 32-col slice
    const int m0   = blockIdx.y * BM;
    const int n0   = blockIdx.x * BN;
    const int gate = blockIdx.x >> 3;   // 0=Z(tanh) 1=F(sig) 2=O(sig)

    float acc[4][4][4];
    #pragma unroll
    for (int i = 0; i < 4; i++)
        #pragma unroll
        for (int j = 0; j < 4; j++)
            #pragma unroll
            for (int c = 0; c < 4; c++) acc[i][j][c] = 0.0f;

    auto issue = [&](int kt, int buf) {
        const uint32_t sA = sA0 + buf * SA_BYTES;
        const uint32_t sB = sB0 + buf * SB_BYTES;
        const float* xb = g_Xr + (size_t)m0 * K_TOT + kt * BK;
        const float* wb = g_Wr + (size_t)n0 * K_TOT + kt * BK;
        #pragma unroll
        for (int i = 0; i < 4; i++) {
            int id = tid + i * 512;
            int r = id >> 3, c = id & 7;
            cp_async16(sA + r * 128 + (((uint32_t)(c ^ (r & 7))) << 4),
                       xb + (size_t)r * K_TOT + c * 4);
        }
        #pragma unroll
        for (int i = 0; i < 2; i++) {
            int id = tid + i * 512;
            int r = id >> 3, c = id & 7;
            cp_async16(sB + r * 128 + (((uint32_t)(c ^ (r & 7))) << 4),
                       wb + (size_t)r * K_TOT + c * 4);
        }
        cp_commit();
    };

    const int l7 = lane & 7;
    const int aRowBase = wm * 64 + ((lane >> 3) & 1) * 8 + l7;   // + i*16
    const int aChunkAdd = (lane >> 4);                            // 0 or 1
    const int bRowBase = wn * 32 + (lane >> 4) * 8 + l7;          // + jb*16
    const int bChunkAdd = ((lane >> 3) & 1);

    issue(0, 0);
    issue(1, 1);
    issue(2, 2);

    for (int kt = 0; kt < KSTEPS; kt++) {
        cp_wait2();                              // group kt complete
        __syncthreads();                         // also protects WAR for issue below
        const int nb = kt + LOOKAHEAD;
        if (nb < KSTEPS) issue(nb, nb % NSTAGE);
        else             cp_commit();            // keep group count consistent

        const int buf = kt % NSTAGE;
        const uint32_t sA = sA0 + buf * SA_BYTES;
        const uint32_t sB = sB0 + buf * SB_BYTES;

        #pragma unroll
        for (int ks = 0; ks < 4; ks++) {
            uint32_t a[4][4], b[4][2];
            const int ac = ks * 2 + aChunkAdd;
            #pragma unroll
            for (int i = 0; i < 4; i++) {
                const int row = aRowBase + i * 16;
                ldsm_x4(a[i], sA + row * 128 + (((uint32_t)(ac ^ l7)) << 4));
            }
            const int bc = ks * 2 + bChunkAdd;
            #pragma unroll
            for (int jb = 0; jb < 2; jb++) {
                uint32_t r[4];
                const int row = bRowBase + jb * 16;
                ldsm_x4(r, sB + row * 128 + (((uint32_t)(bc ^ l7)) << 4));
                b[jb * 2 + 0][0] = r[0]; b[jb * 2 + 0][1] = r[1];
                b[jb * 2 + 1][0] = r[2]; b[jb * 2 + 1][1] = r[3];
            }
            #pragma unroll
            for (int i = 0; i < 4; i++)
                #pragma unroll
                for (int j = 0; j < 4; j++)
                    mma_tf32(acc[i][j], a[i], b[j]);
        }
        // no trailing barrier: next iteration's wait+sync covers buffer reuse
    }

    // ---- epilogue: bias + activation, fp16 (half2) stores ----
    const int lrow = lane >> 2, lcol = lane & 3;
    #pragma unroll
    for (int j = 0; j < 4; j++) {
        const int n = n0 + wn * 32 + j * 8 + lcol * 2;   // even
        const float b0 = __ldg(bias + n);
        const float b1 = __ldg(bias + n + 1);
        #pragma unroll
        for (int i = 0; i < 4; i++) {
            const int m = m0 + wm * 64 + i * 16 + lrow;
            float y0 = acc[i][j][0] + b0, y1 = acc[i][j][1] + b1;
            float y2 = acc[i][j][2] + b0, y3 = acc[i][j][3] + b1;
            float2 v0, v1;
            if (gate == 0) {
                v0 = make_float2(ftanh(y0), ftanh(y1));
                v1 = make_float2(ftanh(y2), ftanh(y3));
            } else {
                v0 = make_float2(fsigmoid(y0), fsigmoid(y1));
                v1 = make_float2(fsigmoid(y2), fsigmoid(y3));
            }
            *(__half2*)&g_yact[(size_t)m * N_TOT + n]       = __float22half2_rn(v0);
            *(__half2*)&g_yact[(size_t)(m + 8) * N_TOT + n] = __float22half2_rn(v1);
        }
    }
}

// ============================================================
// Kernel 2: per-segment affine reduction, 2 channels/thread (half2 loads)
//   a = prod(1-f), c = local scan from 0
// ============================================================
__global__ void __launch_bounds__(128)
scan_partial() {
    const int g = blockIdx.x * 128 + threadIdx.x;       // seg*CH2 + ch2
    const int seg = g >> 13;                            // /CH2
    const int ch2 = g & (CH2 - 1);
    const int b = ch2 >> 9, d2 = ch2 & 511;
    const __half2* Y = (const __half2*)g_yact;          // half2 row length N_TOT/2

    float2 a = make_float2(1.0f, 1.0f);
    float2 c = make_float2(0.0f, 0.0f);
    const int t0 = seg * SEGLEN;
    #pragma unroll 4
    for (int t = t0; t < t0 + SEGLEN; t++) {
        size_t rb = (size_t)(t * BATCH + b) * (N_TOT / 2);
        float2 z = __half22float2(Y[rb + d2]);
        float2 f = __half22float2(Y[rb + (DIM / 2) + d2]);
        c.x = fmaf(f.x, z.x - c.x, c.x);
        c.y = fmaf(f.y, z.y - c.y, c.y);
        a.x *= (1.0f - f.x);
        a.y *= (1.0f - f.y);
    }
    *(float2*)&g_seg_a[seg * CH + ch2 * 2] = a;
    *(float2*)&g_seg_c[seg * CH + ch2 * 2] = c;
}

// ============================================================
// Kernel 3: sequential combine over 32 segments; emits segment start states + C_last
// ============================================================
__global__ void __launch_bounds__(128)
scan_combine(const float* __restrict__ hidden, float* __restrict__ c_last) {
    const int ch2 = blockIdx.x * 128 + threadIdx.x;     // 0..CH2
    float2 s = *(const float2*)&hidden[ch2 * 2];
    #pragma unroll
    for (int p = 0; p < SEGS; p++) {
        *(float2*)&g_seg_s[p * CH + ch2 * 2] = s;
        float2 aa = *(const float2*)&g_seg_a[p * CH + ch2 * 2];
        float2 cc = *(const float2*)&g_seg_c[p * CH + ch2 * 2];
        s.x = fmaf(aa.x, s.x, cc.x);
        s.y = fmaf(aa.y, s.y, cc.y);
    }
    *(float2*)&c_last[ch2 * 2] = s;
}

// ============================================================
// Kernel 4: replay segments from start state, write H = sig(O) * C (2 ch/thread)
// ============================================================
__global__ void __launch_bounds__(128)
scan_final(float* __restrict__ H) {
    const int g = blockIdx.x * 128 + threadIdx.x;
    const int seg = g >> 13;
    const int ch2 = g & (CH2 - 1);
    const int b = ch2 >> 9, d2 = ch2 & 511;
    const __half2* Y = (const __half2*)g_yact;

    float2 h = *(const float2*)&g_seg_s[seg * CH + ch2 * 2];
    const int t0 = seg * SEGLEN;
    #pragma unroll 4
    for (int t = t0; t < t0 + SEGLEN; t++) {
        size_t rb = (size_t)(t * BATCH + b) * (N_TOT / 2);
        float2 z = __half22float2(Y[rb + d2]);
        float2 f = __half22float2(Y[rb + (DIM / 2) + d2]);
        float2 o = __half22float2(Y[rb + DIM + d2]);
        h.x = fmaf(f.x, z.x - h.x, h.x);
        h.y = fmaf(f.y, z.y - h.y, h.y);
        float2 out = make_float2(o.x * h.x, o.y * h.y);
        *(float2*)&H[(size_t)(t * BATCH + b) * DIM + d2 * 2] = out;
    }
}

// ============================================================
// launcher
// ============================================================
extern "C" void kernel_launch(void* const* d_in, const int* in_sizes, int n_in,
                              void* d_out, int out_size) {
    const float* X      = (const float*)d_in[0];   // (S,B,D)
    const float* hidden = (const float*)d_in[1];   // (B,D)
    const float* W      = (const float*)d_in[2];   // (3D,D)
    const float* b      = (const float*)d_in[3];   // (3D,)
    float* out = (float*)d_out;                    // H (S,B,D) then C_last (1,B,D)

    float* xr; cudaGetSymbolAddress((void**)&xr, g_Xr);
    float* wr; cudaGetSymbolAddress((void**)&wr, g_Wr);

    cudaFuncSetAttribute(gemm_gates, cudaFuncAttributeMaxDynamicSharedMemorySize, SMEM_TOTAL);

    round_pass<<<(M_TOT * K_TOT / 4 + 255) / 256, 256>>>(X, xr, M_TOT * K_TOT / 4);
    round_pass<<<(N_TOT * K_TOT / 4 + 255) / 256, 256>>>(W, wr, N_TOT * K_TOT / 4);

    dim3 grid(N_TOT / BN, M_TOT / BM);             // (24, 128)
    gemm_gates<<<grid, 512, SMEM_TOTAL>>>(b);

    scan_partial<<<SEGS * CH2 / 128, 128>>>();
    scan_combine<<<CH2 / 128, 128>>>(hidden, out + (size_t)M_TOT * DIM);
    scan_final<<<SEGS * CH2 / 128, 128>>>(out);
}

// round 6
// speedup vs baseline: 1.8975x; 1.3732x over previous
#include <cuda_runtime.h>
#include <cuda_fp16.h>
#include <cstdint>

// ---------------- problem constants ----------------
#define S_LEN 2048
#define BATCH 16
#define DIM   1024
#define M_TOT (S_LEN*BATCH)      // 32768
#define N_TOT (3*DIM)            // 3072
#define K_TOT DIM                // 1024

// GEMM tiling (fp16 operands, fp32 accum)
#define BM 256
#define BN 128
#define BK 32
#define KSTEPS (K_TOT/BK)        // 32
#define NSTAGE 4
#define LOOKAHEAD 3
#define SA_BYTES (BM*BK*2)       // 16384 per stage
#define SB_BYTES (BN*BK*2)       // 8192 per stage
#define SMEM_TOTAL (NSTAGE*(SA_BYTES+SB_BYTES))   // 98304

// scan partitioning
#define SEGS 32
#define SEGLEN (S_LEN/SEGS)      // 64
#define CH (BATCH*DIM)           // 16384
#define CH2 (CH/2)               // 8192 channel-pairs

// ---------------- device scratch ----------------
__device__ __half g_yact[(size_t)M_TOT * N_TOT]; // activated gates (fp16): tanh(Z), sig(F), sig(O)
__device__ __half g_Xh[(size_t)M_TOT * K_TOT];   // fp16-rounded X
__device__ __half g_Wh[(size_t)N_TOT * K_TOT];   // fp16-rounded W
__device__ float g_seg_a[SEGS*CH];
__device__ float g_seg_c[SEGS*CH];
__device__ float g_seg_s[SEGS*CH];

// ---------------- helpers ----------------
__device__ __forceinline__ uint32_t smem_u32(const void* p) {
    uint32_t a;
    asm("{ .reg .u64 t; cvta.to.shared.u64 t, %1; cvt.u32.u64 %0, t; }" : "=r"(a) : "l"(p));
    return a;
}
__device__ __forceinline__ void cp_async16(uint32_t dst, const void* src) {
    asm volatile("cp.async.cg.shared.global [%0], [%1], 16;" :: "r"(dst), "l"(src) : "memory");
}
__device__ __forceinline__ void cp_commit() {
    asm volatile("cp.async.commit_group;" ::: "memory");
}
__device__ __forceinline__ void cp_wait2() {
    asm volatile("cp.async.wait_group 2;" ::: "memory");
}

__device__ __forceinline__ void ldsm_x4(uint32_t* r, uint32_t addr) {
    asm volatile("ldmatrix.sync.aligned.m8n8.x4.shared.b16 {%0,%1,%2,%3}, [%4];"
        : "=r"(r[0]), "=r"(r[1]), "=r"(r[2]), "=r"(r[3]) : "r"(addr));
}

// mma.sync m16n8k16 fp16 in / fp32 accumulate (baseline PTX, sm_80+)
__device__ __forceinline__ void mma_f16(float* d, const uint32_t* a, const uint32_t* b) {
    asm volatile(
        "mma.sync.aligned.m16n8k16.row.col.f32.f16.f16.f32 "
        "{%0,%1,%2,%3}, {%4,%5,%6,%7}, {%8,%9}, {%0,%1,%2,%3};"
        : "+f"(d[0]), "+f"(d[1]), "+f"(d[2]), "+f"(d[3])
        : "r"(a[0]), "r"(a[1]), "r"(a[2]), "r"(a[3]), "r"(b[0]), "r"(b[1]));
}

__device__ __forceinline__ float fsigmoid(float x) { return 1.0f / (1.0f + __expf(-x)); }
__device__ __forceinline__ float ftanh(float x)    { return 2.0f * fsigmoid(2.0f * x) - 1.0f; }

// smem swizzle for 64B rows (4 x 16B chunks): chunk ^= (row>>1)&3
__device__ __forceinline__ uint32_t swz_addr(uint32_t base, int row, int chunk) {
    return base + row * 64 + (((uint32_t)(chunk ^ ((row >> 1) & 3))) << 4);
}

// ============================================================
// Kernel 0: fp32 -> fp16 conversion (streamed; float4 in, half4 out)
// ============================================================
__global__ void __launch_bounds__(256)
to_half_pass(const float* __restrict__ src, __half* __restrict__ dst, int n4) {
    int i = blockIdx.x * 256 + threadIdx.x;
    if (i >= n4) return;
    float4 v = ((const float4*)src)[i];
    __half2 h0 = __float22half2_rn(make_float2(v.x, v.y));
    __half2 h1 = __float22half2_rn(make_float2(v.z, v.w));
    uint2 packed = make_uint2(*(uint32_t*)&h0, *(uint32_t*)&h1);
    ((uint2*)dst)[i] = packed;
}

// ============================================================
// Kernel 1: Y = act(X @ W^T + b)  via mma.sync fp16 + ldmatrix + 4-stage cp.async
//   grid = (N_TOT/BN, M_TOT/BM) = (24, 128), 512 threads (16 warps, 4m x 4n)
//   smem rows: 64B (BK=32 halves), swizzled
// ============================================================
__global__ void __launch_bounds__(512, 1)
gemm_gates(const float* __restrict__ bias) {
    extern __shared__ char smem[];
    const uint32_t sA0 = smem_u32(smem);                    // 4 stages of A
    const uint32_t sB0 = sA0 + NSTAGE * SA_BYTES;           // 4 stages of B

    const int tid  = threadIdx.x;
    const int lane = tid & 31;
    const int wid  = tid >> 5;          // 0..15
    const int wm   = wid & 3;           // 64-row slice
    const int wn   = wid >> 2;          // 32-col slice
    const int m0   = blockIdx.y * BM;
    const int n0   = blockIdx.x * BN;
    const int gate = blockIdx.x >> 3;   // 0=Z(tanh) 1=F(sig) 2=O(sig)

    float acc[4][4][4];
    #pragma unroll
    for (int i = 0; i < 4; i++)
        #pragma unroll
        for (int j = 0; j < 4; j++)
            #pragma unroll
            for (int c = 0; c < 4; c++) acc[i][j][c] = 0.0f;

    // ---- cp.async fill (16B = 8 halves per chunk; 4 chunks per 64B row) ----
    // A: 1024 chunks -> 2/thread; B: 512 chunks -> 1/thread
    auto issue = [&](int kt, int buf) {
        const uint32_t sA = sA0 + buf * SA_BYTES;
        const uint32_t sB = sB0 + buf * SB_BYTES;
        const __half* xb = g_Xh + (size_t)m0 * K_TOT + kt * BK;
        const __half* wb = g_Wh + (size_t)n0 * K_TOT + kt * BK;
        #pragma unroll
        for (int i = 0; i < 2; i++) {
            int id = tid + i * 512;
            int r = id >> 2, c = id & 3;
            cp_async16(swz_addr(sA, r, c), xb + (size_t)r * K_TOT + c * 8);
        }
        {
            int r = tid >> 2, c = tid & 3;
            cp_async16(swz_addr(sB, r, c), wb + (size_t)r * K_TOT + c * 8);
        }
        cp_commit();
    };

    // ---- per-lane fragment addressing ----
    const int l15 = lane & 15;
    const int lhi = lane >> 4;                 // 0/1 -> k-lo / k-hi chunk
    const int aRowBase = wm * 64 + l15;        // + i*16
    const int bRowBase = wn * 32 + l15;        // + jb*16

    issue(0, 0);
    issue(1, 1);
    issue(2, 2);

    for (int kt = 0; kt < KSTEPS; kt++) {
        cp_wait2();                              // group kt complete
        __syncthreads();                         // also WAR-protects issue below
        const int nb = kt + LOOKAHEAD;
        if (nb < KSTEPS) issue(nb, nb % NSTAGE);
        else             cp_commit();            // keep group count consistent

        const int buf = kt % NSTAGE;
        const uint32_t sA = sA0 + buf * SA_BYTES;
        const uint32_t sB = sB0 + buf * SB_BYTES;

        #pragma unroll
        for (int ks = 0; ks < 2; ks++) {         // two k16 steps per BK=32
            const int chunk = ks * 2 + lhi;
            uint32_t a[4][4], b[4][2];
            #pragma unroll
            for (int i = 0; i < 4; i++)
                ldsm_x4(a[i], swz_addr(sA, aRowBase + i * 16, chunk));
            #pragma unroll
            for (int jb = 0; jb < 2; jb++) {
                uint32_t r[4];
                ldsm_x4(r, swz_addr(sB, bRowBase + jb * 16, chunk));
                b[jb * 2 + 0][0] = r[0]; b[jb * 2 + 0][1] = r[2];
                b[jb * 2 + 1][0] = r[1]; b[jb * 2 + 1][1] = r[3];
            }
            #pragma unroll
            for (int i = 0; i < 4; i++)
                #pragma unroll
                for (int j = 0; j < 4; j++)
                    mma_f16(acc[i][j], a[i], b[j]);
        }
        // no trailing barrier: next iteration's wait+sync covers buffer reuse
    }

    // ---- epilogue: bias + activation, fp16 (half2) stores ----
    const int lrow = lane >> 2, lcol = lane & 3;
    #pragma unroll
    for (int j = 0; j < 4; j++) {
        const int n = n0 + wn * 32 + j * 8 + lcol * 2;   // even
        const float b0 = __ldg(bias + n);
        const float b1 = __ldg(bias + n + 1);
        #pragma unroll
        for (int i = 0; i < 4; i++) {
            const int m = m0 + wm * 64 + i * 16 + lrow;
            float y0 = acc[i][j][0] + b0, y1 = acc[i][j][1] + b1;
            float y2 = acc[i][j][2] + b0, y3 = acc[i][j][3] + b1;
            float2 v0, v1;
            if (gate == 0) {
                v0 = make_float2(ftanh(y0), ftanh(y1));
                v1 = make_float2(ftanh(y2), ftanh(y3));
            } else {
                v0 = make_float2(fsigmoid(y0), fsigmoid(y1));
                v1 = make_float2(fsigmoid(y2), fsigmoid(y3));
            }
            *(__half2*)&g_yact[(size_t)m * N_TOT + n]       = __float22half2_rn(v0);
            *(__half2*)&g_yact[(size_t)(m + 8) * N_TOT + n] = __float22half2_rn(v1);
        }
    }
}

// ============================================================
// Kernel 2: per-segment affine reduction, 2 channels/thread (half2 loads)
//   a = prod(1-f), c = local scan from 0
// ============================================================
__global__ void __launch_bounds__(128)
scan_partial() {
    const int g = blockIdx.x * 128 + threadIdx.x;       // seg*CH2 + ch2
    const int seg = g >> 13;                            // /CH2
    const int ch2 = g & (CH2 - 1);
    const int b = ch2 >> 9, d2 = ch2 & 511;
    const __half2* Y = (const __half2*)g_yact;          // half2 row length N_TOT/2

    float2 a = make_float2(1.0f, 1.0f);
    float2 c = make_float2(0.0f, 0.0f);
    const int t0 = seg * SEGLEN;
    #pragma unroll 4
    for (int t = t0; t < t0 + SEGLEN; t++) {
        size_t rb = (size_t)(t * BATCH + b) * (N_TOT / 2);
        float2 z = __half22float2(Y[rb + d2]);
        float2 f = __half22float2(Y[rb + (DIM / 2) + d2]);
        c.x = fmaf(f.x, z.x - c.x, c.x);
        c.y = fmaf(f.y, z.y - c.y, c.y);
        a.x *= (1.0f - f.x);
        a.y *= (1.0f - f.y);
    }
    *(float2*)&g_seg_a[seg * CH + ch2 * 2] = a;
    *(float2*)&g_seg_c[seg * CH + ch2 * 2] = c;
}

// ============================================================
// Kernel 3: sequential combine over 32 segments; emits segment start states + C_last
// ============================================================
__global__ void __launch_bounds__(128)
scan_combine(const float* __restrict__ hidden, float* __restrict__ c_last) {
    const int ch2 = blockIdx.x * 128 + threadIdx.x;     // 0..CH2
    float2 s = *(const float2*)&hidden[ch2 * 2];
    #pragma unroll
    for (int p = 0; p < SEGS; p++) {
        *(float2*)&g_seg_s[p * CH + ch2 * 2] = s;
        float2 aa = *(const float2*)&g_seg_a[p * CH + ch2 * 2];
        float2 cc = *(const float2*)&g_seg_c[p * CH + ch2 * 2];
        s.x = fmaf(aa.x, s.x, cc.x);
        s.y = fmaf(aa.y, s.y, cc.y);
    }
    *(float2*)&c_last[ch2 * 2] = s;
}

// ============================================================
// Kernel 4: replay segments from start state, write H = sig(O) * C (2 ch/thread)
// ============================================================
__global__ void __launch_bounds__(128)
scan_final(float* __restrict__ H) {
    const int g = blockIdx.x * 128 + threadIdx.x;
    const int seg = g >> 13;
    const int ch2 = g & (CH2 - 1);
    const int b = ch2 >> 9, d2 = ch2 & 511;
    const __half2* Y = (const __half2*)g_yact;

    float2 h = *(const float2*)&g_seg_s[seg * CH + ch2 * 2];
    const int t0 = seg * SEGLEN;
    #pragma unroll 4
    for (int t = t0; t < t0 + SEGLEN; t++) {
        size_t rb = (size_t)(t * BATCH + b) * (N_TOT / 2);
        float2 z = __half22float2(Y[rb + d2]);
        float2 f = __half22float2(Y[rb + (DIM / 2) + d2]);
        float2 o = __half22float2(Y[rb + DIM + d2]);
        h.x = fmaf(f.x, z.x - h.x, h.x);
        h.y = fmaf(f.y, z.y - h.y, h.y);
        float2 out = make_float2(o.x * h.x, o.y * h.y);
        *(float2*)&H[(size_t)(t * BATCH + b) * DIM + d2 * 2] = out;
    }
}

// ============================================================
// launcher
// ============================================================
extern "C" void kernel_launch(void* const* d_in, const int* in_sizes, int n_in,
                              void* d_out, int out_size) {
    const float* X      = (const float*)d_in[0];   // (S,B,D)
    const float* hidden = (const float*)d_in[1];   // (B,D)
    const float* W      = (const float*)d_in[2];   // (3D,D)
    const float* b      = (const float*)d_in[3];   // (3D,)
    float* out = (float*)d_out;                    // H (S,B,D) then C_last (1,B,D)

    __half* xh; cudaGetSymbolAddress((void**)&xh, g_Xh);
    __half* wh; cudaGetSymbolAddress((void**)&wh, g_Wh);

    cudaFuncSetAttribute(gemm_gates, cudaFuncAttributeMaxDynamicSharedMemorySize, SMEM_TOTAL);

    to_half_pass<<<(M_TOT * K_TOT / 4 + 255) / 256, 256>>>(X, xh, M_TOT * K_TOT / 4);
    to_half_pass<<<(N_TOT * K_TOT / 4 + 255) / 256, 256>>>(W, wh, N_TOT * K_TOT / 4);

    dim3 grid(N_TOT / BN, M_TOT / BM);             // (24, 128)
    gemm_gates<<<grid, 512, SMEM_TOTAL>>>(b);

    scan_partial<<<SEGS * CH2 / 128, 128>>>();
    scan_combine<<<CH2 / 128, 128>>>(hidden, out + (size_t)M_TOT * DIM);
    scan_final<<<SEGS * CH2 / 128, 128>>>(out);
}